// round 12
// baseline (speedup 1.0000x reference)
#include <cuda_runtime.h>
#include <cuda_bf16.h>
#include <cuda_fp16.h>

#define NODES 20000
#define INF_  128
#define HD    64
#define NH    2
#define DD    32
#define EDG   320000
#define RREL  5
#define KHOP  3

// ---------------- device scratch (static, no allocation) ----------------
__device__ float  g_x[RREL][NODES * HD];              // hop-0 projected feats (fp32)
__device__ float  g_hops[KHOP][RREL][NODES * HD];     // hops 1..K (fp32, for hop_mix)
__device__ __half2 g_xh[RREL][NODES * 32];            // fp16 shadow of g_x (gather input)
__device__ __half2 g_hh[2][RREL][NODES * 32];         // fp16 shadow of hops 1..2 (gather input)
__device__ float  g_acc[NODES * HD];                  // residual accumulator (from res GEMM)
__device__ float4 g_elr[RREL][NODES];                 // {el_h0, er_h0, el_h1, er_h1}
__device__ float4 g_adj[RREL][EDG];                   // {src(bits), alpha0, alpha1, pad} CSR order
__device__ int    g_csr_src[RREL][EDG];               // src ids grouped by dst
__device__ int    g_rank[RREL * EDG];                 // within-dst rank from count pass
__device__ int    g_deg[RREL * NODES];
__device__ int    g_off[RREL][NODES + 1];
__device__ float  g_w[8];
__device__ float  g_wres[INF_ * HD];                  // sum_r w_r * res_w[r]

// ---------------- helpers ----------------
__device__ __forceinline__ float wsum(float v) {
    v += __shfl_xor_sync(0xffffffffu, v, 16);
    v += __shfl_xor_sync(0xffffffffu, v, 8);
    v += __shfl_xor_sync(0xffffffffu, v, 4);
    v += __shfl_xor_sync(0xffffffffu, v, 2);
    v += __shfl_xor_sync(0xffffffffu, v, 1);
    return v;
}
__device__ __forceinline__ float wmax(float v) {
    v = fmaxf(v, __shfl_xor_sync(0xffffffffu, v, 16));
    v = fmaxf(v, __shfl_xor_sync(0xffffffffu, v, 8));
    v = fmaxf(v, __shfl_xor_sync(0xffffffffu, v, 4));
    v = fmaxf(v, __shfl_xor_sync(0xffffffffu, v, 2));
    v = fmaxf(v, __shfl_xor_sync(0xffffffffu, v, 1));
    return v;
}
__device__ __forceinline__ void fma4(float4& acc, float a, const float4 w) {
    acc.x = fmaf(a, w.x, acc.x);
    acc.y = fmaf(a, w.y, acc.y);
    acc.z = fmaf(a, w.z, acc.z);
    acc.w = fmaf(a, w.w, acc.w);
}
__device__ __forceinline__ float dot4(const float4 a, const float4 b) {
    return a.x * b.x + a.y * b.y + a.z * b.z + a.w * b.w;
}

// ---------------- setup: relation weights + combined residual W ----------------
__global__ void setup_kernel(const float* __restrict__ w_rel, const float* __restrict__ b_rel,
                             const float* __restrict__ rsw) {
    __shared__ float sw[RREL];
    int t = threadIdx.x;  // 1024
    if (t < RREL) {
        float s = b_rel[t];
#pragma unroll
        for (int j = 0; j < RREL; j++) s += w_rel[t * RREL + j];
        sw[t] = s;
        g_w[t] = s;
    }
    __syncthreads();
    float w0 = sw[0], w1 = sw[1], w2 = sw[2], w3 = sw[3], w4 = sw[4];
    for (int i = t; i < INF_ * HD; i += 1024) {
        float s = w0 * rsw[0 * INF_ * HD + i];
        s = fmaf(w1, rsw[1 * INF_ * HD + i], s);
        s = fmaf(w2, rsw[2 * INF_ * HD + i], s);
        s = fmaf(w3, rsw[3 * INF_ * HD + i], s);
        s = fmaf(w4, rsw[4 * INF_ * HD + i], s);
        g_wres[i] = s;
    }
}

// ---------------- CSR build ----------------
__global__ void csr_count(const int* __restrict__ dst) {
    int t = blockIdx.x * blockDim.x + threadIdx.x;   // RREL*EDG exact
    int r = t / EDG;
    g_rank[t] = atomicAdd(&g_deg[r * NODES + dst[t]], 1);
}

__global__ void csr_scan() {
    int r = blockIdx.x;
    int t = threadIdx.x;
    int lane = t & 31, warp = t >> 5;
    __shared__ int wtot[32];
    int base = t * 20;
    int local[20];
    int s = 0;
#pragma unroll
    for (int i = 0; i < 20; i++) {
        int idx = base + i;
        local[i] = s;
        if (idx < NODES) s += g_deg[r * NODES + idx];
    }
    int v = s;
#pragma unroll
    for (int o = 1; o < 32; o <<= 1) {
        int u = __shfl_up_sync(0xffffffffu, v, o);
        if (lane >= o) v += u;
    }
    if (lane == 31) wtot[warp] = v;
    __syncthreads();
    if (warp == 0) {
        int x = wtot[lane];
#pragma unroll
        for (int o = 1; o < 32; o <<= 1) {
            int u = __shfl_up_sync(0xffffffffu, x, o);
            if (lane >= o) x += u;
        }
        wtot[lane] = x;
    }
    __syncthreads();
    int wbase = (warp == 0) ? 0 : wtot[warp - 1];
    int excl = wbase + v - s;
#pragma unroll
    for (int i = 0; i < 20; i++) {
        int idx = base + i;
        if (idx < NODES) g_off[r][idx] = excl + local[i];
    }
    if (t == 0) g_off[r][NODES] = EDG;
}

__global__ void csr_fill(const int* __restrict__ src, const int* __restrict__ dst) {
    int t = blockIdx.x * blockDim.x + threadIdx.x;   // RREL*EDG exact
    int r = t / EDG;
    int d = dst[t];
    g_csr_src[r][g_off[r][d] + g_rank[t]] = src[t];
}

// ---------------- GEMM: out[N,64] = A[N,128] @ W[128,64], fused attn + fp16 shadow ----------------
__global__ void gemm_all(const float* __restrict__ A, const float* __restrict__ fcw,
                         const float* __restrict__ al, const float* __restrict__ ar) {
    int r = blockIdx.y;
    const float* __restrict__ W = (r < RREL) ? (fcw + (size_t)r * INF_ * HD) : g_wres;
    float* __restrict__ out = (r < RREL) ? g_x[r] : g_acc;

    int tx = threadIdx.x & 15;
    int ty = threadIdx.x >> 4;
    int row0 = blockIdx.x * 32 + ty * 2;
    const float4* A4 = reinterpret_cast<const float4*>(A);
    const float4* W4 = reinterpret_cast<const float4*>(W);
    float4 acc0 = {0, 0, 0, 0}, acc1 = {0, 0, 0, 0};
    int a0 = row0 * 32, a1 = a0 + 32;
#pragma unroll 8
    for (int kk = 0; kk < 32; kk++) {
        float4 ha = A4[a0 + kk];
        float4 hb = A4[a1 + kk];
        float4 w0 = W4[(4 * kk + 0) * 16 + tx];
        float4 w1 = W4[(4 * kk + 1) * 16 + tx];
        float4 w2 = W4[(4 * kk + 2) * 16 + tx];
        float4 w3 = W4[(4 * kk + 3) * 16 + tx];
        fma4(acc0, ha.x, w0); fma4(acc0, ha.y, w1); fma4(acc0, ha.z, w2); fma4(acc0, ha.w, w3);
        fma4(acc1, hb.x, w0); fma4(acc1, hb.y, w1); fma4(acc1, hb.z, w2); fma4(acc1, hb.w, w3);
    }
    float4* O4 = reinterpret_cast<float4*>(out);
    O4[row0 * 16 + tx] = acc0;
    O4[(row0 + 1) * 16 + tx] = acc1;

    if (r < RREL) {
        // fp16 shadow for gather passes
        g_xh[r][row0 * 32 + 2 * tx]           = __float22half2_rn(make_float2(acc0.x, acc0.y));
        g_xh[r][row0 * 32 + 2 * tx + 1]       = __float22half2_rn(make_float2(acc0.z, acc0.w));
        g_xh[r][(row0 + 1) * 32 + 2 * tx]     = __float22half2_rn(make_float2(acc1.x, acc1.y));
        g_xh[r][(row0 + 1) * 32 + 2 * tx + 1] = __float22half2_rn(make_float2(acc1.z, acc1.w));

        const float4* al4 = reinterpret_cast<const float4*>(al + r * HD);
        const float4* ar4 = reinterpret_cast<const float4*>(ar + r * HD);
        float4 av = al4[tx], bv = ar4[tx];
        float pl0 = dot4(acc0, av), pr0 = dot4(acc0, bv);
        float pl1 = dot4(acc1, av), pr1 = dot4(acc1, bv);
#pragma unroll
        for (int o = 1; o < 8; o <<= 1) {
            pl0 += __shfl_xor_sync(0xffffffffu, pl0, o);
            pr0 += __shfl_xor_sync(0xffffffffu, pr0, o);
            pl1 += __shfl_xor_sync(0xffffffffu, pl1, o);
            pr1 += __shfl_xor_sync(0xffffffffu, pr1, o);
        }
        if ((tx & 7) == 0) {
            int hh = tx >> 3;
            reinterpret_cast<float2*>(&g_elr[r][row0])[hh]     = make_float2(pl0, pr0);
            reinterpret_cast<float2*>(&g_elr[r][row0 + 1])[hh] = make_float2(pl1, pr1);
        }
    }
}

// ---------------- fused per-dst softmax + hop-0 gather (fp16 gather input) ----------------
__global__ void softmax_hop0() {
    int gt = blockIdx.x * blockDim.x + threadIdx.x;
    int w = gt >> 5, lane = gt & 31;                 // w in [0, RREL*NODES), exact grid
    int r = w / NODES, d = w - r * NODES;
    int off = g_off[r][d], deg = g_off[r][d + 1] - off;
    const __half2* __restrict__ hin = g_xh[r];
    float2 acc = {0.f, 0.f};

    if (deg == 0) {
        reinterpret_cast<float2*>(g_hops[0][r] + (d << 6))[lane] = acc;
        g_hh[0][r][(d << 5) + lane] = __float22half2_rn(acc);
        return;
    }
    float4 dv = g_elr[r][d];
    float er0 = dv.y, er1 = dv.w;

    if (deg <= 32) {
        int s = 0;
        float l0 = -1e30f, l1 = -1e30f;
        if (lane < deg) {
            s = g_csr_src[r][off + lane];
            float4 sv = g_elr[r][s];
            l0 = sv.x + er0;
            l1 = sv.z + er1;
            l0 = l0 > 0.f ? l0 : 0.2f * l0;
            l1 = l1 > 0.f ? l1 : 0.2f * l1;
        }
        float m0 = wmax(l0), m1 = wmax(l1);
        float e0 = (lane < deg) ? __expf(l0 - m0) : 0.f;
        float e1 = (lane < deg) ? __expf(l1 - m1) : 0.f;
        float s0 = wsum(e0), s1 = wsum(e1);
        float a0 = e0 / fmaxf(s0, 1e-9f);
        float a1 = e1 / fmaxf(s1, 1e-9f);
        if (lane < deg)
            g_adj[r][off + lane] = make_float4(__int_as_float(s), a0, a1, 0.f);
#pragma unroll 4
        for (int j = 0; j < deg; j++) {
            int   sj  = __shfl_sync(0xffffffffu, s, j);
            float a0j = __shfl_sync(0xffffffffu, a0, j);
            float a1j = __shfl_sync(0xffffffffu, a1, j);
            float aj = (lane < 16) ? a0j : a1j;
            float2 v = __half22float2(hin[(sj << 5) + lane]);
            acc.x = fmaf(aj, v.x, acc.x);
            acc.y = fmaf(aj, v.y, acc.y);
        }
    } else {
        // generic path (rare, deg>32)
        float m0 = -1e30f, m1 = -1e30f;
        for (int i = lane; i < deg; i += 32) {
            int s = g_csr_src[r][off + i];
            float4 sv = g_elr[r][s];
            float l0 = sv.x + er0;
            float l1 = sv.z + er1;
            l0 = l0 > 0.f ? l0 : 0.2f * l0;
            l1 = l1 > 0.f ? l1 : 0.2f * l1;
            g_adj[r][off + i] = make_float4(__int_as_float(s), l0, l1, 0.f);
            m0 = fmaxf(m0, l0);
            m1 = fmaxf(m1, l1);
        }
        m0 = wmax(m0); m1 = wmax(m1);
        float s0 = 0.f, s1 = 0.f;
        for (int i = lane; i < deg; i += 32) {
            float4 q = g_adj[r][off + i];
            q.y = __expf(q.y - m0);
            q.z = __expf(q.z - m1);
            g_adj[r][off + i] = q;
            s0 += q.y; s1 += q.z;
        }
        s0 = wsum(s0); s1 = wsum(s1);
        float i0 = 1.f / fmaxf(s0, 1e-9f);
        float i1 = 1.f / fmaxf(s1, 1e-9f);
        for (int c = 0; c < deg; c += 32) {
            int i = c + lane;
            int s = 0; float a0 = 0.f, a1 = 0.f;
            if (i < deg) {
                float4 q = g_adj[r][off + i];
                s = __float_as_int(q.x);
                a0 = q.y * i0; a1 = q.z * i1;
                g_adj[r][off + i] = make_float4(q.x, a0, a1, 0.f);
            }
            int lim = min(32, deg - c);
            for (int j = 0; j < lim; j++) {
                int   sj  = __shfl_sync(0xffffffffu, s, j);
                float a0j = __shfl_sync(0xffffffffu, a0, j);
                float a1j = __shfl_sync(0xffffffffu, a1, j);
                float aj = (lane < 16) ? a0j : a1j;
                float2 v = __half22float2(hin[(sj << 5) + lane]);
                acc.x = fmaf(aj, v.x, acc.x);
                acc.y = fmaf(aj, v.y, acc.y);
            }
        }
    }
    reinterpret_cast<float2*>(g_hops[0][r] + (d << 6))[lane] = acc;
    g_hh[0][r][(d << 5) + lane] = __float22half2_rn(acc);
}

// ---------------- diffusion hops 1..K-1: fp16 gather, fp32 accumulate ----------------
__global__ void hop_gather(int k) {
    int gt = blockIdx.x * blockDim.x + threadIdx.x;
    int w = gt >> 5, lane = gt & 31;                 // warp per (r,dst)
    int r = w / NODES, d = w - r * NODES;
    int off = g_off[r][d], deg = g_off[r][d + 1] - off;
    const __half2* __restrict__ hin = g_hh[k - 1][r];
    const float4* __restrict__ rec = g_adj[r] + off;
    bool hi = lane >= 16;
    float2 acc = {0.f, 0.f};
#pragma unroll 4
    for (int i = 0; i < deg; i++) {
        float4 q = rec[i];                           // uniform -> warp broadcast, 1 line
        int s = __float_as_int(q.x);
        float a = hi ? q.z : q.y;
        float2 v = __half22float2(hin[(s << 5) + lane]);
        acc.x = fmaf(a, v.x, acc.x);
        acc.y = fmaf(a, v.y, acc.y);
    }
    reinterpret_cast<float2*>(g_hops[k][r] + (d << 6))[lane] = acc;
    if (k < KHOP - 1)                                 // last hop's fp16 shadow never read
        g_hh[k][r][(d << 5) + lane] = __float22half2_rn(acc);
}

// ---------------- hop attention + mix + relation accumulate + head-mean ----------------
__global__ void hop_mix_final(const float* __restrict__ hal, const float* __restrict__ har,
                              float* __restrict__ out) {
    __shared__ float s1[4][32];
    int gt = blockIdx.x * blockDim.x + threadIdx.x;
    int w = gt >> 5, lane = gt & 31;                 // w in [0, NODES*NH)
    int n = w >> 1, hh = w & 1;
    int wib = (threadIdx.x >> 5);
    int base = (n << 6) + (hh << 5) + lane;
    float accv = g_acc[base];
#pragma unroll
    for (int r = 0; r < RREL; r++) {
        float a_l = hal[r * HD + hh * DD + lane];
        float a_r = har[r * HD + hh * DD + lane];
        float nh[KHOP + 1], lg[KHOP + 1];
#pragma unroll
        for (int k = 0; k < KHOP + 1; k++) {
            float v = (k == 0) ? g_x[r][base] : g_hops[k - 1][r][base];
            float ss = wsum(v * v);
            float sc = 1.f / fmaxf(sqrtf(ss), 1e-9f);
            nh[k] = v * sc;
            lg[k] = wsum(nh[k] * a_l);
        }
        float hr = wsum(nh[0] * a_r);
        float m = -1e30f;
#pragma unroll
        for (int k = 0; k < KHOP + 1; k++) {
            float x = lg[k] + hr;
            lg[k] = x > 0.f ? x : 0.2f * x;
            m = fmaxf(m, lg[k]);
        }
        float s = 0.f, wk[KHOP + 1];
#pragma unroll
        for (int k = 0; k < KHOP + 1; k++) { wk[k] = __expf(lg[k] - m); s += wk[k]; }
        float inv = 1.f / s;
        float mix = 0.f;
#pragma unroll
        for (int k = 0; k < KHOP + 1; k++) mix = fmaf(wk[k] * inv, nh[k], mix);
        accv = fmaf(g_w[r], mix, accv);
    }
    if (hh == 1) s1[wib >> 1][lane] = accv;
    __syncthreads();
    if (hh == 0) out[n * DD + lane] = 0.5f * (accv + s1[wib >> 1][lane]);
}

// ---------------- launch ----------------
extern "C" void kernel_launch(void* const* d_in, const int* in_sizes, int n_in,
                              void* d_out, int out_size) {
    const float* h    = (const float*)d_in[0];
    const int*   src  = (const int*)d_in[1];
    const int*   dst  = (const int*)d_in[2];
    const float* fcw  = (const float*)d_in[3];
    const float* rsw  = (const float*)d_in[4];
    const float* al   = (const float*)d_in[5];
    const float* ar   = (const float*)d_in[6];
    const float* hal  = (const float*)d_in[7];
    const float* har  = (const float*)d_in[8];
    const float* wrel = (const float*)d_in[9];
    const float* brel = (const float*)d_in[10];
    float* out = (float*)d_out;

    void* deg_p = nullptr;
    cudaGetSymbolAddress(&deg_p, g_deg);

    setup_kernel<<<1, 1024>>>(wrel, brel, rsw);
    cudaMemsetAsync(deg_p, 0, (size_t)RREL * NODES * sizeof(int), 0);

    const int reBlocks = (RREL * EDG) / 256;                 // 6250 exact
    csr_count<<<reBlocks, 256>>>(dst);
    csr_scan<<<RREL, 1024>>>();
    csr_fill<<<reBlocks, 256>>>(src, dst);

    dim3 gg(NODES / 32, RREL + 1);
    gemm_all<<<gg, 256>>>(h, fcw, al, ar);

    const int wBlocks = (RREL * NODES * 32) / 256;           // 12500 exact
    softmax_hop0<<<wBlocks, 256>>>();
    for (int k = 1; k < KHOP; k++)
        hop_gather<<<wBlocks, 256>>>(k);

    hop_mix_final<<<(NODES * NH * 32) / 256, 256>>>(hal, har, out);
}

// round 13
// speedup vs baseline: 1.0138x; 1.0138x over previous
#include <cuda_runtime.h>
#include <cuda_bf16.h>

#define NODES 20000
#define INF_  128
#define HD    64
#define NH    2
#define DD    32
#define EDG   320000
#define RREL  5
#define KHOP  3

// ---------------- device scratch (static, no allocation) ----------------
__device__ float  g_x[RREL][NODES * HD];              // hop-0 projected feats
__device__ float  g_hops[KHOP][RREL][NODES * HD];     // hops 1..K
__device__ float  g_acc[NODES * HD];                  // residual accumulator (from res GEMM)
__device__ float4 g_elr[RREL][NODES];                 // {el_h0, er_h0, el_h1, er_h1}
__device__ float4 g_adj[RREL][EDG];                   // {src(bits), alpha0, alpha1, pad} CSR order
__device__ int    g_csr_src[RREL][EDG];               // src ids grouped by dst
__device__ int    g_rank[RREL * EDG];                 // within-dst rank from count pass
__device__ int    g_deg[RREL * NODES];
__device__ int    g_off[RREL][NODES + 1];
__device__ float  g_w[8];
__device__ float  g_wres[INF_ * HD];                  // sum_r w_r * res_w[r]

// ---------------- helpers ----------------
__device__ __forceinline__ float wsum(float v) {
    v += __shfl_xor_sync(0xffffffffu, v, 16);
    v += __shfl_xor_sync(0xffffffffu, v, 8);
    v += __shfl_xor_sync(0xffffffffu, v, 4);
    v += __shfl_xor_sync(0xffffffffu, v, 2);
    v += __shfl_xor_sync(0xffffffffu, v, 1);
    return v;
}
__device__ __forceinline__ float wmax(float v) {
    v = fmaxf(v, __shfl_xor_sync(0xffffffffu, v, 16));
    v = fmaxf(v, __shfl_xor_sync(0xffffffffu, v, 8));
    v = fmaxf(v, __shfl_xor_sync(0xffffffffu, v, 4));
    v = fmaxf(v, __shfl_xor_sync(0xffffffffu, v, 2));
    v = fmaxf(v, __shfl_xor_sync(0xffffffffu, v, 1));
    return v;
}
__device__ __forceinline__ float dot4(const float4 a, const float4 b) {
    return a.x * b.x + a.y * b.y + a.z * b.z + a.w * b.w;
}

// packed f32x2 FMA (sm_100+; FFMA2 in SASS — only reachable via PTX)
__device__ __forceinline__ unsigned long long pack2s(float x) {
    unsigned long long r;
    asm("mov.b64 %0, {%1, %1};" : "=l"(r) : "f"(x));
    return r;
}
__device__ __forceinline__ void fma2(unsigned long long& c, unsigned long long a,
                                     unsigned long long b) {
    asm("fma.rn.f32x2 %0, %1, %2, %3;" : "=l"(c) : "l"(a), "l"(b), "l"(c));
}
__device__ __forceinline__ float2 unpack2(unsigned long long v) {
    float x, y;
    asm("mov.b64 {%0, %1}, %2;" : "=f"(x), "=f"(y) : "l"(v));
    return make_float2(x, y);
}

// ---------------- setup: relation weights + combined residual W ----------------
__global__ void setup_kernel(const float* __restrict__ w_rel, const float* __restrict__ b_rel,
                             const float* __restrict__ rsw) {
    __shared__ float sw[RREL];
    int t = threadIdx.x;  // 1024
    if (t < RREL) {
        float s = b_rel[t];
#pragma unroll
        for (int j = 0; j < RREL; j++) s += w_rel[t * RREL + j];
        sw[t] = s;
        g_w[t] = s;
    }
    __syncthreads();
    float w0 = sw[0], w1 = sw[1], w2 = sw[2], w3 = sw[3], w4 = sw[4];
    for (int i = t; i < INF_ * HD; i += 1024) {
        float s = w0 * rsw[0 * INF_ * HD + i];
        s = fmaf(w1, rsw[1 * INF_ * HD + i], s);
        s = fmaf(w2, rsw[2 * INF_ * HD + i], s);
        s = fmaf(w3, rsw[3 * INF_ * HD + i], s);
        s = fmaf(w4, rsw[4 * INF_ * HD + i], s);
        g_wres[i] = s;
    }
}

// ---------------- CSR build ----------------
__global__ void csr_count(const int* __restrict__ dst) {
    int t = blockIdx.x * blockDim.x + threadIdx.x;   // RREL*EDG exact
    int r = t / EDG;
    g_rank[t] = atomicAdd(&g_deg[r * NODES + dst[t]], 1);
}

__global__ void csr_scan() {
    int r = blockIdx.x;
    int t = threadIdx.x;
    int lane = t & 31, warp = t >> 5;
    __shared__ int wtot[32];
    int base = t * 20;
    int local[20];
    int s = 0;
#pragma unroll
    for (int i = 0; i < 20; i++) {
        int idx = base + i;
        local[i] = s;
        if (idx < NODES) s += g_deg[r * NODES + idx];
    }
    int v = s;
#pragma unroll
    for (int o = 1; o < 32; o <<= 1) {
        int u = __shfl_up_sync(0xffffffffu, v, o);
        if (lane >= o) v += u;
    }
    if (lane == 31) wtot[warp] = v;
    __syncthreads();
    if (warp == 0) {
        int x = wtot[lane];
#pragma unroll
        for (int o = 1; o < 32; o <<= 1) {
            int u = __shfl_up_sync(0xffffffffu, x, o);
            if (lane >= o) x += u;
        }
        wtot[lane] = x;
    }
    __syncthreads();
    int wbase = (warp == 0) ? 0 : wtot[warp - 1];
    int excl = wbase + v - s;
#pragma unroll
    for (int i = 0; i < 20; i++) {
        int idx = base + i;
        if (idx < NODES) g_off[r][idx] = excl + local[i];
    }
    if (t == 0) g_off[r][NODES] = EDG;
}

__global__ void csr_fill(const int* __restrict__ src, const int* __restrict__ dst) {
    int t = blockIdx.x * blockDim.x + threadIdx.x;   // RREL*EDG exact
    int r = t / EDG;
    int d = dst[t];
    g_csr_src[r][g_off[r][d] + g_rank[t]] = src[t];
}

// ---------------- GEMM: out[N,64] = A[N,128] @ W[128,64], f32x2 packed, fused attn ----------------
__global__ void gemm_all(const float* __restrict__ A, const float* __restrict__ fcw,
                         const float* __restrict__ al, const float* __restrict__ ar) {
    int r = blockIdx.y;
    const float* __restrict__ W = (r < RREL) ? (fcw + (size_t)r * INF_ * HD) : g_wres;
    float* __restrict__ out = (r < RREL) ? g_x[r] : g_acc;

    int tx = threadIdx.x & 15;
    int ty = threadIdx.x >> 4;
    int row0 = blockIdx.x * 32 + ty * 2;
    const float4* A4 = reinterpret_cast<const float4*>(A);
    const ulonglong2* W2 = reinterpret_cast<const ulonglong2*>(W);  // pair-packed cols
    unsigned long long r0a = 0ull, r0b = 0ull, r1a = 0ull, r1b = 0ull;
    int a0 = row0 * 32, a1 = a0 + 32;
#pragma unroll 8
    for (int kk = 0; kk < 32; kk++) {
        float4 ha = A4[a0 + kk];
        float4 hb = A4[a1 + kk];
        ulonglong2 w0 = W2[(4 * kk + 0) * 16 + tx];
        ulonglong2 w1 = W2[(4 * kk + 1) * 16 + tx];
        ulonglong2 w2 = W2[(4 * kk + 2) * 16 + tx];
        ulonglong2 w3 = W2[(4 * kk + 3) * 16 + tx];
        unsigned long long p;
        p = pack2s(ha.x); fma2(r0a, p, w0.x); fma2(r0b, p, w0.y);
        p = pack2s(ha.y); fma2(r0a, p, w1.x); fma2(r0b, p, w1.y);
        p = pack2s(ha.z); fma2(r0a, p, w2.x); fma2(r0b, p, w2.y);
        p = pack2s(ha.w); fma2(r0a, p, w3.x); fma2(r0b, p, w3.y);
        p = pack2s(hb.x); fma2(r1a, p, w0.x); fma2(r1b, p, w0.y);
        p = pack2s(hb.y); fma2(r1a, p, w1.x); fma2(r1b, p, w1.y);
        p = pack2s(hb.z); fma2(r1a, p, w2.x); fma2(r1b, p, w2.y);
        p = pack2s(hb.w); fma2(r1a, p, w3.x); fma2(r1b, p, w3.y);
    }
    float2 u0 = unpack2(r0a), u1 = unpack2(r0b);
    float2 u2 = unpack2(r1a), u3 = unpack2(r1b);
    float4 acc0 = make_float4(u0.x, u0.y, u1.x, u1.y);
    float4 acc1 = make_float4(u2.x, u2.y, u3.x, u3.y);

    float4* O4 = reinterpret_cast<float4*>(out);
    O4[row0 * 16 + tx] = acc0;
    O4[(row0 + 1) * 16 + tx] = acc1;

    if (r < RREL) {
        const float4* al4 = reinterpret_cast<const float4*>(al + r * HD);
        const float4* ar4 = reinterpret_cast<const float4*>(ar + r * HD);
        float4 av = al4[tx], bv = ar4[tx];
        float pl0 = dot4(acc0, av), pr0 = dot4(acc0, bv);
        float pl1 = dot4(acc1, av), pr1 = dot4(acc1, bv);
#pragma unroll
        for (int o = 1; o < 8; o <<= 1) {
            pl0 += __shfl_xor_sync(0xffffffffu, pl0, o);
            pr0 += __shfl_xor_sync(0xffffffffu, pr0, o);
            pl1 += __shfl_xor_sync(0xffffffffu, pl1, o);
            pr1 += __shfl_xor_sync(0xffffffffu, pr1, o);
        }
        if ((tx & 7) == 0) {
            int hh = tx >> 3;
            reinterpret_cast<float2*>(&g_elr[r][row0])[hh]     = make_float2(pl0, pr0);
            reinterpret_cast<float2*>(&g_elr[r][row0 + 1])[hh] = make_float2(pl1, pr1);
        }
    }
}

// ---------------- fused per-dst softmax + hop-0 gather (2 edges/iter, half-warps) ----------------
__global__ void softmax_hop0() {
    int gt = blockIdx.x * blockDim.x + threadIdx.x;
    int w = gt >> 5, lane = gt & 31;                 // w in [0, RREL*NODES), exact grid
    int r = w / NODES, d = w - r * NODES;
    int off = g_off[r][d], deg = g_off[r][d + 1] - off;
    const float4* __restrict__ hin4 = reinterpret_cast<const float4*>(g_x[r]);
    float4* __restrict__ out4 = reinterpret_cast<float4*>(g_hops[0][r]);
    int half = lane >> 4, hl = lane & 15;

    if (deg == 0) {
        if (half == 0) out4[(d << 4) + hl] = make_float4(0.f, 0.f, 0.f, 0.f);
        return;
    }
    float4 dv = g_elr[r][d];
    float er0 = dv.y, er1 = dv.w;

    if (deg <= 32) {
        // softmax entirely in registers (lane i holds edge i)
        int s = 0;
        float l0 = -1e30f, l1 = -1e30f;
        if (lane < deg) {
            s = g_csr_src[r][off + lane];
            float4 sv = g_elr[r][s];
            l0 = sv.x + er0;
            l1 = sv.z + er1;
            l0 = l0 > 0.f ? l0 : 0.2f * l0;
            l1 = l1 > 0.f ? l1 : 0.2f * l1;
        }
        float m0 = wmax(l0), m1 = wmax(l1);
        float e0 = (lane < deg) ? __expf(l0 - m0) : 0.f;
        float e1 = (lane < deg) ? __expf(l1 - m1) : 0.f;
        float s0 = wsum(e0), s1 = wsum(e1);
        float a0 = e0 / fmaxf(s0, 1e-9f);
        float a1 = e1 / fmaxf(s1, 1e-9f);
        if (lane < deg)
            g_adj[r][off + lane] = make_float4(__int_as_float(s), a0, a1, 0.f);

        // gather: 2 edges per iteration, one per half-warp, float4 per lane
        float4 acc = make_float4(0.f, 0.f, 0.f, 0.f);
        for (int j = 0; j < deg; j += 2) {
            int e = j + half;
            int sj  = __shfl_sync(0xffffffffu, s, e & 31);
            float a0j = __shfl_sync(0xffffffffu, a0, e & 31);
            float a1j = __shfl_sync(0xffffffffu, a1, e & 31);
            float a = (hl < 8) ? a0j : a1j;
            if (e >= deg) a = 0.f;
            float4 v = hin4[(sj << 4) + hl];
            acc.x = fmaf(a, v.x, acc.x);
            acc.y = fmaf(a, v.y, acc.y);
            acc.z = fmaf(a, v.z, acc.z);
            acc.w = fmaf(a, v.w, acc.w);
        }
        acc.x += __shfl_xor_sync(0xffffffffu, acc.x, 16);
        acc.y += __shfl_xor_sync(0xffffffffu, acc.y, 16);
        acc.z += __shfl_xor_sync(0xffffffffu, acc.z, 16);
        acc.w += __shfl_xor_sync(0xffffffffu, acc.w, 16);
        if (half == 0) out4[(d << 4) + hl] = acc;
    } else {
        // generic path (rare, deg>32): 3 passes through g_adj, float2 gather
        float m0 = -1e30f, m1 = -1e30f;
        for (int i = lane; i < deg; i += 32) {
            int s = g_csr_src[r][off + i];
            float4 sv = g_elr[r][s];
            float l0 = sv.x + er0;
            float l1 = sv.z + er1;
            l0 = l0 > 0.f ? l0 : 0.2f * l0;
            l1 = l1 > 0.f ? l1 : 0.2f * l1;
            g_adj[r][off + i] = make_float4(__int_as_float(s), l0, l1, 0.f);
            m0 = fmaxf(m0, l0);
            m1 = fmaxf(m1, l1);
        }
        m0 = wmax(m0); m1 = wmax(m1);
        float s0 = 0.f, s1 = 0.f;
        for (int i = lane; i < deg; i += 32) {
            float4 q = g_adj[r][off + i];
            q.y = __expf(q.y - m0);
            q.z = __expf(q.z - m1);
            g_adj[r][off + i] = q;
            s0 += q.y; s1 += q.z;
        }
        s0 = wsum(s0); s1 = wsum(s1);
        float i0 = 1.f / fmaxf(s0, 1e-9f);
        float i1 = 1.f / fmaxf(s1, 1e-9f);
        for (int i = lane; i < deg; i += 32) {
            float4 q = g_adj[r][off + i];
            g_adj[r][off + i] = make_float4(q.x, q.y * i0, q.z * i1, 0.f);
        }
        __syncwarp();
        const float* __restrict__ hin = g_x[r];
        float2 acc = {0.f, 0.f};
        for (int i = 0; i < deg; i++) {
            float4 q = g_adj[r][off + i];
            int s = __float_as_int(q.x);
            float a = (lane < 16) ? q.y : q.z;
            float2 v = reinterpret_cast<const float2*>(hin + (s << 6))[lane];
            acc.x = fmaf(a, v.x, acc.x);
            acc.y = fmaf(a, v.y, acc.y);
        }
        reinterpret_cast<float2*>(g_hops[0][r] + (d << 6))[lane] = acc;
    }
}

// ---------------- diffusion hops 1..K-1: 2 edges/iter, half-warps, float4 ----------------
__global__ void hop_gather(int k) {
    int gt = blockIdx.x * blockDim.x + threadIdx.x;
    int w = gt >> 5, lane = gt & 31;                 // warp per (r,dst)
    int r = w / NODES, d = w - r * NODES;
    int off = g_off[r][d], deg = g_off[r][d + 1] - off;
    const float4* __restrict__ hin4 = reinterpret_cast<const float4*>(g_hops[k - 1][r]);
    const float4* __restrict__ rec = g_adj[r] + off;
    int half = lane >> 4, hl = lane & 15;
    float4 acc = make_float4(0.f, 0.f, 0.f, 0.f);
#pragma unroll 2
    for (int i = 0; i < deg; i += 2) {
        int e = i + half;
        int idx = (e < deg) ? e : (deg - 1);
        float4 q = rec[idx];                         // per-half uniform load
        int s = __float_as_int(q.x);
        float a = (hl < 8) ? q.y : q.z;
        if (e >= deg) a = 0.f;
        float4 v = hin4[(s << 4) + hl];
        acc.x = fmaf(a, v.x, acc.x);
        acc.y = fmaf(a, v.y, acc.y);
        acc.z = fmaf(a, v.z, acc.z);
        acc.w = fmaf(a, v.w, acc.w);
    }
    acc.x += __shfl_xor_sync(0xffffffffu, acc.x, 16);
    acc.y += __shfl_xor_sync(0xffffffffu, acc.y, 16);
    acc.z += __shfl_xor_sync(0xffffffffu, acc.z, 16);
    acc.w += __shfl_xor_sync(0xffffffffu, acc.w, 16);
    if (half == 0)
        reinterpret_cast<float4*>(g_hops[k][r])[(d << 4) + hl] = acc;
}

// ---------------- hop attention + mix + relation accumulate + head-mean ----------------
__global__ void hop_mix_final(const float* __restrict__ hal, const float* __restrict__ har,
                              float* __restrict__ out) {
    __shared__ float s1[4][32];
    int gt = blockIdx.x * blockDim.x + threadIdx.x;
    int w = gt >> 5, lane = gt & 31;                 // w in [0, NODES*NH)
    int n = w >> 1, hh = w & 1;
    int wib = (threadIdx.x >> 5);
    int base = (n << 6) + (hh << 5) + lane;
    float accv = g_acc[base];
#pragma unroll
    for (int r = 0; r < RREL; r++) {
        float a_l = hal[r * HD + hh * DD + lane];
        float a_r = har[r * HD + hh * DD + lane];
        float nh[KHOP + 1], lg[KHOP + 1];
#pragma unroll
        for (int k = 0; k < KHOP + 1; k++) {
            float v = (k == 0) ? g_x[r][base] : g_hops[k - 1][r][base];
            float ss = wsum(v * v);
            float sc = 1.f / fmaxf(sqrtf(ss), 1e-9f);
            nh[k] = v * sc;
            lg[k] = wsum(nh[k] * a_l);
        }
        float hr = wsum(nh[0] * a_r);
        float m = -1e30f;
#pragma unroll
        for (int k = 0; k < KHOP + 1; k++) {
            float x = lg[k] + hr;
            lg[k] = x > 0.f ? x : 0.2f * x;
            m = fmaxf(m, lg[k]);
        }
        float s = 0.f, wk[KHOP + 1];
#pragma unroll
        for (int k = 0; k < KHOP + 1; k++) { wk[k] = __expf(lg[k] - m); s += wk[k]; }
        float inv = 1.f / s;
        float mix = 0.f;
#pragma unroll
        for (int k = 0; k < KHOP + 1; k++) mix = fmaf(wk[k] * inv, nh[k], mix);
        accv = fmaf(g_w[r], mix, accv);
    }
    if (hh == 1) s1[wib >> 1][lane] = accv;
    __syncthreads();
    if (hh == 0) out[n * DD + lane] = 0.5f * (accv + s1[wib >> 1][lane]);
}

// ---------------- launch ----------------
extern "C" void kernel_launch(void* const* d_in, const int* in_sizes, int n_in,
                              void* d_out, int out_size) {
    const float* h    = (const float*)d_in[0];
    const int*   src  = (const int*)d_in[1];
    const int*   dst  = (const int*)d_in[2];
    const float* fcw  = (const float*)d_in[3];
    const float* rsw  = (const float*)d_in[4];
    const float* al   = (const float*)d_in[5];
    const float* ar   = (const float*)d_in[6];
    const float* hal  = (const float*)d_in[7];
    const float* har  = (const float*)d_in[8];
    const float* wrel = (const float*)d_in[9];
    const float* brel = (const float*)d_in[10];
    float* out = (float*)d_out;

    void* deg_p = nullptr;
    cudaGetSymbolAddress(&deg_p, g_deg);

    setup_kernel<<<1, 1024>>>(wrel, brel, rsw);
    cudaMemsetAsync(deg_p, 0, (size_t)RREL * NODES * sizeof(int), 0);

    const int reBlocks = (RREL * EDG) / 256;                 // 6250 exact
    csr_count<<<reBlocks, 256>>>(dst);
    csr_scan<<<RREL, 1024>>>();
    csr_fill<<<reBlocks, 256>>>(src, dst);

    dim3 gg(NODES / 32, RREL + 1);
    gemm_all<<<gg, 256>>>(h, fcw, al, ar);

    const int wBlocks = (RREL * NODES * 32) / 256;           // 12500 exact
    softmax_hop0<<<wBlocks, 256>>>();
    for (int k = 1; k < KHOP; k++)
        hop_gather<<<wBlocks, 256>>>(k);

    hop_mix_final<<<(NODES * NH * 32) / 256, 256>>>(hal, har, out);
}

// round 14
// speedup vs baseline: 1.0298x; 1.0158x over previous
#include <cuda_runtime.h>
#include <cuda_bf16.h>

#define NODES 20000
#define INF_  128
#define HD    64
#define NH    2
#define DD    32
#define EDG   320000
#define RREL  5
#define KHOP  3

// ---------------- device scratch (static, no allocation) ----------------
__device__ float  g_x[RREL][NODES * HD];              // hop-0 projected feats
__device__ float  g_hops[KHOP][RREL][NODES * HD];     // hops 1..K
__device__ float  g_acc[NODES * HD];                  // residual accumulator (from res GEMM)
__device__ float4 g_elr[RREL][NODES];                 // {el_h0, er_h0, el_h1, er_h1}
__device__ float4 g_adj[RREL][EDG];                   // {src(bits), alpha0, alpha1, pad} CSR order
__device__ int    g_csr_src[RREL][EDG];               // src ids grouped by dst
__device__ int    g_rank[RREL * EDG];                 // within-dst rank from count pass
__device__ int    g_deg[RREL * NODES];
__device__ int    g_off[RREL][NODES + 1];
__device__ float  g_w[8];
__device__ float  g_wres[INF_ * HD];                  // sum_r w_r * res_w[r]

// ---------------- helpers ----------------
__device__ __forceinline__ float wsum(float v) {
    v += __shfl_xor_sync(0xffffffffu, v, 16);
    v += __shfl_xor_sync(0xffffffffu, v, 8);
    v += __shfl_xor_sync(0xffffffffu, v, 4);
    v += __shfl_xor_sync(0xffffffffu, v, 2);
    v += __shfl_xor_sync(0xffffffffu, v, 1);
    return v;
}
__device__ __forceinline__ float wmax(float v) {
    v = fmaxf(v, __shfl_xor_sync(0xffffffffu, v, 16));
    v = fmaxf(v, __shfl_xor_sync(0xffffffffu, v, 8));
    v = fmaxf(v, __shfl_xor_sync(0xffffffffu, v, 4));
    v = fmaxf(v, __shfl_xor_sync(0xffffffffu, v, 2));
    v = fmaxf(v, __shfl_xor_sync(0xffffffffu, v, 1));
    return v;
}
__device__ __forceinline__ float dot4(const float4 a, const float4 b) {
    return a.x * b.x + a.y * b.y + a.z * b.z + a.w * b.w;
}

// packed f32x2 FMA (sm_100+; FFMA2 in SASS — only reachable via PTX)
__device__ __forceinline__ unsigned long long pack2s(float x) {
    unsigned long long r;
    asm("mov.b64 %0, {%1, %1};" : "=l"(r) : "f"(x));
    return r;
}
__device__ __forceinline__ void fma2(unsigned long long& c, unsigned long long a,
                                     unsigned long long b) {
    asm("fma.rn.f32x2 %0, %1, %2, %3;" : "=l"(c) : "l"(a), "l"(b), "l"(c));
}
__device__ __forceinline__ float2 unpack2(unsigned long long v) {
    float x, y;
    asm("mov.b64 {%0, %1}, %2;" : "=f"(x), "=f"(y) : "l"(v));
    return make_float2(x, y);
}

// ---------------- setup: relation weights + combined residual W ----------------
__global__ void setup_kernel(const float* __restrict__ w_rel, const float* __restrict__ b_rel,
                             const float* __restrict__ rsw) {
    __shared__ float sw[RREL];
    int t = threadIdx.x;  // 1024
    if (t < RREL) {
        float s = b_rel[t];
#pragma unroll
        for (int j = 0; j < RREL; j++) s += w_rel[t * RREL + j];
        sw[t] = s;
        g_w[t] = s;
    }
    __syncthreads();
    float w0 = sw[0], w1 = sw[1], w2 = sw[2], w3 = sw[3], w4 = sw[4];
    for (int i = t; i < INF_ * HD; i += 1024) {
        float s = w0 * rsw[0 * INF_ * HD + i];
        s = fmaf(w1, rsw[1 * INF_ * HD + i], s);
        s = fmaf(w2, rsw[2 * INF_ * HD + i], s);
        s = fmaf(w3, rsw[3 * INF_ * HD + i], s);
        s = fmaf(w4, rsw[4 * INF_ * HD + i], s);
        g_wres[i] = s;
    }
}

// ---------------- CSR build ----------------
__global__ void csr_count(const int* __restrict__ dst) {
    int t = blockIdx.x * blockDim.x + threadIdx.x;   // RREL*EDG exact
    int r = t / EDG;
    g_rank[t] = atomicAdd(&g_deg[r * NODES + dst[t]], 1);
}

__global__ void csr_scan() {
    int r = blockIdx.x;
    int t = threadIdx.x;
    int lane = t & 31, warp = t >> 5;
    __shared__ int wtot[32];
    int base = t * 20;
    int local[20];
    int s = 0;
#pragma unroll
    for (int i = 0; i < 20; i++) {
        int idx = base + i;
        local[i] = s;
        if (idx < NODES) s += g_deg[r * NODES + idx];
    }
    int v = s;
#pragma unroll
    for (int o = 1; o < 32; o <<= 1) {
        int u = __shfl_up_sync(0xffffffffu, v, o);
        if (lane >= o) v += u;
    }
    if (lane == 31) wtot[warp] = v;
    __syncthreads();
    if (warp == 0) {
        int x = wtot[lane];
#pragma unroll
        for (int o = 1; o < 32; o <<= 1) {
            int u = __shfl_up_sync(0xffffffffu, x, o);
            if (lane >= o) x += u;
        }
        wtot[lane] = x;
    }
    __syncthreads();
    int wbase = (warp == 0) ? 0 : wtot[warp - 1];
    int excl = wbase + v - s;
#pragma unroll
    for (int i = 0; i < 20; i++) {
        int idx = base + i;
        if (idx < NODES) g_off[r][idx] = excl + local[i];
    }
    if (t == 0) g_off[r][NODES] = EDG;
}

__global__ void csr_fill(const int* __restrict__ src, const int* __restrict__ dst) {
    int t = blockIdx.x * blockDim.x + threadIdx.x;   // RREL*EDG exact
    int r = t / EDG;
    int d = dst[t];
    g_csr_src[r][g_off[r][d] + g_rank[t]] = src[t];
}

// ---------------- GEMM: out[N,64] = A[N,128] @ W[128,64], f32x2 packed, fused attn ----------------
__global__ void gemm_all(const float* __restrict__ A, const float* __restrict__ fcw,
                         const float* __restrict__ al, const float* __restrict__ ar) {
    int r = blockIdx.y;
    const float* __restrict__ W = (r < RREL) ? (fcw + (size_t)r * INF_ * HD) : g_wres;
    float* __restrict__ out = (r < RREL) ? g_x[r] : g_acc;

    int tx = threadIdx.x & 15;
    int ty = threadIdx.x >> 4;
    int row0 = blockIdx.x * 32 + ty * 2;
    const float4* A4 = reinterpret_cast<const float4*>(A);
    const ulonglong2* W2 = reinterpret_cast<const ulonglong2*>(W);  // pair-packed cols
    unsigned long long r0a = 0ull, r0b = 0ull, r1a = 0ull, r1b = 0ull;
    int a0 = row0 * 32, a1 = a0 + 32;
#pragma unroll 8
    for (int kk = 0; kk < 32; kk++) {
        float4 ha = A4[a0 + kk];
        float4 hb = A4[a1 + kk];
        ulonglong2 w0 = W2[(4 * kk + 0) * 16 + tx];
        ulonglong2 w1 = W2[(4 * kk + 1) * 16 + tx];
        ulonglong2 w2 = W2[(4 * kk + 2) * 16 + tx];
        ulonglong2 w3 = W2[(4 * kk + 3) * 16 + tx];
        unsigned long long p;
        p = pack2s(ha.x); fma2(r0a, p, w0.x); fma2(r0b, p, w0.y);
        p = pack2s(ha.y); fma2(r0a, p, w1.x); fma2(r0b, p, w1.y);
        p = pack2s(ha.z); fma2(r0a, p, w2.x); fma2(r0b, p, w2.y);
        p = pack2s(ha.w); fma2(r0a, p, w3.x); fma2(r0b, p, w3.y);
        p = pack2s(hb.x); fma2(r1a, p, w0.x); fma2(r1b, p, w0.y);
        p = pack2s(hb.y); fma2(r1a, p, w1.x); fma2(r1b, p, w1.y);
        p = pack2s(hb.z); fma2(r1a, p, w2.x); fma2(r1b, p, w2.y);
        p = pack2s(hb.w); fma2(r1a, p, w3.x); fma2(r1b, p, w3.y);
    }
    float2 u0 = unpack2(r0a), u1 = unpack2(r0b);
    float2 u2 = unpack2(r1a), u3 = unpack2(r1b);
    float4 acc0 = make_float4(u0.x, u0.y, u1.x, u1.y);
    float4 acc1 = make_float4(u2.x, u2.y, u3.x, u3.y);

    float4* O4 = reinterpret_cast<float4*>(out);
    O4[row0 * 16 + tx] = acc0;
    O4[(row0 + 1) * 16 + tx] = acc1;

    if (r < RREL) {
        const float4* al4 = reinterpret_cast<const float4*>(al + r * HD);
        const float4* ar4 = reinterpret_cast<const float4*>(ar + r * HD);
        float4 av = al4[tx], bv = ar4[tx];
        float pl0 = dot4(acc0, av), pr0 = dot4(acc0, bv);
        float pl1 = dot4(acc1, av), pr1 = dot4(acc1, bv);
#pragma unroll
        for (int o = 1; o < 8; o <<= 1) {
            pl0 += __shfl_xor_sync(0xffffffffu, pl0, o);
            pr0 += __shfl_xor_sync(0xffffffffu, pr0, o);
            pl1 += __shfl_xor_sync(0xffffffffu, pl1, o);
            pr1 += __shfl_xor_sync(0xffffffffu, pr1, o);
        }
        if ((tx & 7) == 0) {
            int hh = tx >> 3;
            reinterpret_cast<float2*>(&g_elr[r][row0])[hh]     = make_float2(pl0, pr0);
            reinterpret_cast<float2*>(&g_elr[r][row0 + 1])[hh] = make_float2(pl1, pr1);
        }
    }
}

// ---------------- fused per-dst softmax + hop-0 gather (warp per (r,dst)) ----------------
__global__ void softmax_hop0() {
    int gt = blockIdx.x * blockDim.x + threadIdx.x;
    int w = gt >> 5, lane = gt & 31;                 // w in [0, RREL*NODES), exact grid
    int r = w / NODES, d = w - r * NODES;
    int off = g_off[r][d], deg = g_off[r][d + 1] - off;
    const float* __restrict__ hin = g_x[r];
    float2 acc = {0.f, 0.f};

    if (deg == 0) {
        reinterpret_cast<float2*>(g_hops[0][r] + (d << 6))[lane] = acc;
        return;
    }
    float4 dv = g_elr[r][d];
    float er0 = dv.y, er1 = dv.w;

    if (deg <= 32) {
        int s = 0;
        float l0 = -1e30f, l1 = -1e30f;
        if (lane < deg) {
            s = g_csr_src[r][off + lane];
            float4 sv = g_elr[r][s];
            l0 = sv.x + er0;
            l1 = sv.z + er1;
            l0 = l0 > 0.f ? l0 : 0.2f * l0;
            l1 = l1 > 0.f ? l1 : 0.2f * l1;
        }
        float m0 = wmax(l0), m1 = wmax(l1);
        float e0 = (lane < deg) ? __expf(l0 - m0) : 0.f;
        float e1 = (lane < deg) ? __expf(l1 - m1) : 0.f;
        float s0 = wsum(e0), s1 = wsum(e1);
        float a0 = e0 / fmaxf(s0, 1e-9f);
        float a1 = e1 / fmaxf(s1, 1e-9f);
        if (lane < deg)
            g_adj[r][off + lane] = make_float4(__int_as_float(s), a0, a1, 0.f);
#pragma unroll 4
        for (int j = 0; j < deg; j++) {
            int   sj  = __shfl_sync(0xffffffffu, s, j);
            float a0j = __shfl_sync(0xffffffffu, a0, j);
            float a1j = __shfl_sync(0xffffffffu, a1, j);
            float aj = (lane < 16) ? a0j : a1j;
            float2 v = reinterpret_cast<const float2*>(hin + (sj << 6))[lane];
            acc.x = fmaf(aj, v.x, acc.x);
            acc.y = fmaf(aj, v.y, acc.y);
        }
    } else {
        // generic path (rare, deg>32)
        float m0 = -1e30f, m1 = -1e30f;
        for (int i = lane; i < deg; i += 32) {
            int s = g_csr_src[r][off + i];
            float4 sv = g_elr[r][s];
            float l0 = sv.x + er0;
            float l1 = sv.z + er1;
            l0 = l0 > 0.f ? l0 : 0.2f * l0;
            l1 = l1 > 0.f ? l1 : 0.2f * l1;
            g_adj[r][off + i] = make_float4(__int_as_float(s), l0, l1, 0.f);
            m0 = fmaxf(m0, l0);
            m1 = fmaxf(m1, l1);
        }
        m0 = wmax(m0); m1 = wmax(m1);
        float s0 = 0.f, s1 = 0.f;
        for (int i = lane; i < deg; i += 32) {
            float4 q = g_adj[r][off + i];
            q.y = __expf(q.y - m0);
            q.z = __expf(q.z - m1);
            g_adj[r][off + i] = q;
            s0 += q.y; s1 += q.z;
        }
        s0 = wsum(s0); s1 = wsum(s1);
        float i0 = 1.f / fmaxf(s0, 1e-9f);
        float i1 = 1.f / fmaxf(s1, 1e-9f);
        for (int c = 0; c < deg; c += 32) {
            int i = c + lane;
            int s = 0; float a0 = 0.f, a1 = 0.f;
            if (i < deg) {
                float4 q = g_adj[r][off + i];
                s = __float_as_int(q.x);
                a0 = q.y * i0; a1 = q.z * i1;
                g_adj[r][off + i] = make_float4(q.x, a0, a1, 0.f);
            }
            int lim = min(32, deg - c);
            for (int j = 0; j < lim; j++) {
                int   sj  = __shfl_sync(0xffffffffu, s, j);
                float a0j = __shfl_sync(0xffffffffu, a0, j);
                float a1j = __shfl_sync(0xffffffffu, a1, j);
                float aj = (lane < 16) ? a0j : a1j;
                float2 v = reinterpret_cast<const float2*>(hin + (sj << 6))[lane];
                acc.x = fmaf(aj, v.x, acc.x);
                acc.y = fmaf(aj, v.y, acc.y);
            }
        }
    }
    reinterpret_cast<float2*>(g_hops[0][r] + (d << 6))[lane] = acc;
}

// ---------------- diffusion hops 1..K-1: uniform record loop ----------------
__global__ void hop_gather(int k) {
    int gt = blockIdx.x * blockDim.x + threadIdx.x;
    int w = gt >> 5, lane = gt & 31;                 // warp per (r,dst)
    int r = w / NODES, d = w - r * NODES;
    int off = g_off[r][d], deg = g_off[r][d + 1] - off;
    const float* __restrict__ hin = g_hops[k - 1][r];
    const float4* __restrict__ rec = g_adj[r] + off;
    bool hi = lane >= 16;
    float2 acc = {0.f, 0.f};
#pragma unroll 4
    for (int i = 0; i < deg; i++) {
        float4 q = rec[i];                           // uniform -> warp broadcast, 1 line
        int s = __float_as_int(q.x);
        float a = hi ? q.z : q.y;
        float2 v = reinterpret_cast<const float2*>(hin + (s << 6))[lane];
        acc.x = fmaf(a, v.x, acc.x);
        acc.y = fmaf(a, v.y, acc.y);
    }
    reinterpret_cast<float2*>(g_hops[k][r] + (d << 6))[lane] = acc;
}

// ---------------- hop attention + mix + relation accumulate + head-mean ----------------
__global__ void hop_mix_final(const float* __restrict__ hal, const float* __restrict__ har,
                              float* __restrict__ out) {
    __shared__ float s1[4][32];
    int gt = blockIdx.x * blockDim.x + threadIdx.x;
    int w = gt >> 5, lane = gt & 31;                 // w in [0, NODES*NH)
    int n = w >> 1, hh = w & 1;
    int wib = (threadIdx.x >> 5);
    int base = (n << 6) + (hh << 5) + lane;
    float accv = g_acc[base];
#pragma unroll
    for (int r = 0; r < RREL; r++) {
        float a_l = hal[r * HD + hh * DD + lane];
        float a_r = har[r * HD + hh * DD + lane];
        float nh[KHOP + 1], lg[KHOP + 1];
#pragma unroll
        for (int k = 0; k < KHOP + 1; k++) {
            float v = (k == 0) ? g_x[r][base] : g_hops[k - 1][r][base];
            float ss = wsum(v * v);
            float sc = 1.f / fmaxf(sqrtf(ss), 1e-9f);
            nh[k] = v * sc;
            lg[k] = wsum(nh[k] * a_l);
        }
        float hr = wsum(nh[0] * a_r);
        float m = -1e30f;
#pragma unroll
        for (int k = 0; k < KHOP + 1; k++) {
            float x = lg[k] + hr;
            lg[k] = x > 0.f ? x : 0.2f * x;
            m = fmaxf(m, lg[k]);
        }
        float s = 0.f, wk[KHOP + 1];
#pragma unroll
        for (int k = 0; k < KHOP + 1; k++) { wk[k] = __expf(lg[k] - m); s += wk[k]; }
        float inv = 1.f / s;
        float mix = 0.f;
#pragma unroll
        for (int k = 0; k < KHOP + 1; k++) mix = fmaf(wk[k] * inv, nh[k], mix);
        accv = fmaf(g_w[r], mix, accv);
    }
    if (hh == 1) s1[wib >> 1][lane] = accv;
    __syncthreads();
    if (hh == 0) out[n * DD + lane] = 0.5f * (accv + s1[wib >> 1][lane]);
}

// ---------------- launch: fork/join so CSR build overlaps setup+GEMM ----------------
extern "C" void kernel_launch(void* const* d_in, const int* in_sizes, int n_in,
                              void* d_out, int out_size) {
    const float* h    = (const float*)d_in[0];
    const int*   src  = (const int*)d_in[1];
    const int*   dst  = (const int*)d_in[2];
    const float* fcw  = (const float*)d_in[3];
    const float* rsw  = (const float*)d_in[4];
    const float* al   = (const float*)d_in[5];
    const float* ar   = (const float*)d_in[6];
    const float* hal  = (const float*)d_in[7];
    const float* har  = (const float*)d_in[8];
    const float* wrel = (const float*)d_in[9];
    const float* brel = (const float*)d_in[10];
    float* out = (float*)d_out;

    // one-time host-side resources (no device allocation)
    static cudaStream_t s2 = nullptr;
    static cudaEvent_t evRoot = nullptr, evCsr = nullptr;
    if (s2 == nullptr) {
        cudaStreamCreateWithFlags(&s2, cudaStreamNonBlocking);
        cudaEventCreateWithFlags(&evRoot, cudaEventDisableTiming);
        cudaEventCreateWithFlags(&evCsr, cudaEventDisableTiming);
    }

    void* deg_p = nullptr;
    cudaGetSymbolAddress(&deg_p, g_deg);

    const int reBlocks = (RREL * EDG) / 256;                 // 6250 exact

    // fork: side stream builds CSR while main stream does setup + GEMMs
    cudaEventRecord(evRoot, 0);
    cudaStreamWaitEvent(s2, evRoot, 0);

    // side stream: CSR chain
    cudaMemsetAsync(deg_p, 0, (size_t)RREL * NODES * sizeof(int), s2);
    csr_count<<<reBlocks, 256, 0, s2>>>(dst);
    csr_scan<<<RREL, 1024, 0, s2>>>();
    csr_fill<<<reBlocks, 256, 0, s2>>>(src, dst);
    cudaEventRecord(evCsr, s2);

    // main stream: setup + 5 fc GEMMs (+attn epilogue) + combined residual GEMM
    setup_kernel<<<1, 1024>>>(wrel, brel, rsw);
    dim3 gg(NODES / 32, RREL + 1);
    gemm_all<<<gg, 256>>>(h, fcw, al, ar);

    // join: softmax needs both CSR and GEMM results
    cudaStreamWaitEvent(0, evCsr, 0);

    const int wBlocks = (RREL * NODES * 32) / 256;           // 12500 exact
    softmax_hop0<<<wBlocks, 256>>>();
    for (int k = 1; k < KHOP; k++)
        hop_gather<<<wBlocks, 256>>>(k);

    hop_mix_final<<<(NODES * NH * 32) / 256, 256>>>(hal, har, out);
}

// round 17
// speedup vs baseline: 1.1627x; 1.1290x over previous
#include <cuda_runtime.h>
#include <cuda_bf16.h>

#define NODES 20000
#define INF_  128
#define HD    64
#define NH    2
#define DD    32
#define EDG   320000
#define RREL  5
#define KHOP  3

// ---------------- device scratch (static, no allocation) ----------------
__device__ float  g_x[RREL][NODES * HD];              // hop-0 projected feats
__device__ float  g_hops[KHOP][RREL][NODES * HD];     // hops 1..K
__device__ float  g_acc[NODES * HD];                  // residual accumulator (from res GEMM)
__device__ float4 g_elr[RREL][NODES];                 // {el_h0, er_h0, el_h1, er_h1}
__device__ float4 g_adj[RREL][EDG];                   // {src(bits), alpha0, alpha1, pad} CSR order
__device__ int    g_csr_src[RREL][EDG];               // src ids grouped by dst
__device__ int    g_rank[RREL * EDG];                 // within-dst rank from count pass
__device__ int    g_deg[RREL * NODES];
__device__ int    g_off[RREL][NODES + 1];
__device__ float  g_w[8];
__device__ float  g_wres[INF_ * HD];                  // sum_r w_r * res_w[r]

// ---------------- helpers ----------------
__device__ __forceinline__ float wsum(float v) {
    v += __shfl_xor_sync(0xffffffffu, v, 16);
    v += __shfl_xor_sync(0xffffffffu, v, 8);
    v += __shfl_xor_sync(0xffffffffu, v, 4);
    v += __shfl_xor_sync(0xffffffffu, v, 2);
    v += __shfl_xor_sync(0xffffffffu, v, 1);
    return v;
}
__device__ __forceinline__ float wmax(float v) {
    v = fmaxf(v, __shfl_xor_sync(0xffffffffu, v, 16));
    v = fmaxf(v, __shfl_xor_sync(0xffffffffu, v, 8));
    v = fmaxf(v, __shfl_xor_sync(0xffffffffu, v, 4));
    v = fmaxf(v, __shfl_xor_sync(0xffffffffu, v, 2));
    v = fmaxf(v, __shfl_xor_sync(0xffffffffu, v, 1));
    return v;
}
// 4-lane reduction (within groups of 4 consecutive lanes)
__device__ __forceinline__ float qsum(float v) {
    v += __shfl_xor_sync(0xffffffffu, v, 1);
    v += __shfl_xor_sync(0xffffffffu, v, 2);
    return v;
}
__device__ __forceinline__ float dot4(const float4 a, const float4 b) {
    return a.x * b.x + a.y * b.y + a.z * b.z + a.w * b.w;
}

// packed f32x2 FMA (sm_100+; FFMA2 in SASS — only reachable via PTX)
__device__ __forceinline__ unsigned long long pack2s(float x) {
    unsigned long long r;
    asm("mov.b64 %0, {%1, %1};" : "=l"(r) : "f"(x));
    return r;
}
__device__ __forceinline__ void fma2(unsigned long long& c, unsigned long long a,
                                     unsigned long long b) {
    asm("fma.rn.f32x2 %0, %1, %2, %3;" : "=l"(c) : "l"(a), "l"(b), "l"(c));
}
__device__ __forceinline__ float2 unpack2(unsigned long long v) {
    float x, y;
    asm("mov.b64 {%0, %1}, %2;" : "=f"(x), "=f"(y) : "l"(v));
    return make_float2(x, y);
}

// ---------------- setup: relation weights + combined residual W (multi-block) ----------------
__global__ void setup_kernel(const float* __restrict__ w_rel, const float* __restrict__ b_rel,
                             const float* __restrict__ rsw) {
    // every block recomputes the 5 relation weights (trivial) to stay independent
    float sw[RREL];
#pragma unroll
    for (int r = 0; r < RREL; r++) {
        float s = b_rel[r];
#pragma unroll
        for (int j = 0; j < RREL; j++) s += w_rel[r * RREL + j];
        sw[r] = s;
    }
    int i = blockIdx.x * blockDim.x + threadIdx.x;   // 16*512 = 8192 exact
    if (i == 0) {
#pragma unroll
        for (int r = 0; r < RREL; r++) g_w[r] = sw[r];
    }
    float s = sw[0] * rsw[0 * INF_ * HD + i];
    s = fmaf(sw[1], rsw[1 * INF_ * HD + i], s);
    s = fmaf(sw[2], rsw[2 * INF_ * HD + i], s);
    s = fmaf(sw[3], rsw[3 * INF_ * HD + i], s);
    s = fmaf(sw[4], rsw[4 * INF_ * HD + i], s);
    g_wres[i] = s;
}

// ---------------- CSR build ----------------
__global__ void csr_count(const int* __restrict__ dst) {
    int t = blockIdx.x * blockDim.x + threadIdx.x;   // RREL*EDG exact
    int r = t / EDG;
    g_rank[t] = atomicAdd(&g_deg[r * NODES + dst[t]], 1);
}

__global__ void csr_scan() {
    int r = blockIdx.x;
    int t = threadIdx.x;
    int lane = t & 31, warp = t >> 5;
    __shared__ int wtot[32];
    int base = t * 20;
    int local[20];
    int s = 0;
#pragma unroll
    for (int i = 0; i < 20; i++) {
        int idx = base + i;
        local[i] = s;
        if (idx < NODES) s += g_deg[r * NODES + idx];
    }
    int v = s;
#pragma unroll
    for (int o = 1; o < 32; o <<= 1) {
        int u = __shfl_up_sync(0xffffffffu, v, o);
        if (lane >= o) v += u;
    }
    if (lane == 31) wtot[warp] = v;
    __syncthreads();
    if (warp == 0) {
        int x = wtot[lane];
#pragma unroll
        for (int o = 1; o < 32; o <<= 1) {
            int u = __shfl_up_sync(0xffffffffu, x, o);
            if (lane >= o) x += u;
        }
        wtot[lane] = x;
    }
    __syncthreads();
    int wbase = (warp == 0) ? 0 : wtot[warp - 1];
    int excl = wbase + v - s;
#pragma unroll
    for (int i = 0; i < 20; i++) {
        int idx = base + i;
        if (idx < NODES) g_off[r][idx] = excl + local[i];
    }
    if (t == 0) g_off[r][NODES] = EDG;
}

__global__ void csr_fill(const int* __restrict__ src, const int* __restrict__ dst) {
    int t = blockIdx.x * blockDim.x + threadIdx.x;   // RREL*EDG exact
    int r = t / EDG;
    int d = dst[t];
    g_csr_src[r][g_off[r][d] + g_rank[t]] = src[t];
}

// ---------------- GEMM: out[N,64] = A[N,128] @ W[128,64], f32x2 packed, fused attn ----------------
__global__ void gemm_all(const float* __restrict__ A, const float* __restrict__ fcw,
                         const float* __restrict__ al, const float* __restrict__ ar) {
    int r = blockIdx.y;
    const float* __restrict__ W = (r < RREL) ? (fcw + (size_t)r * INF_ * HD) : g_wres;
    float* __restrict__ out = (r < RREL) ? g_x[r] : g_acc;

    int tx = threadIdx.x & 15;
    int ty = threadIdx.x >> 4;
    int row0 = blockIdx.x * 32 + ty * 2;
    const float4* A4 = reinterpret_cast<const float4*>(A);
    const ulonglong2* W2 = reinterpret_cast<const ulonglong2*>(W);  // pair-packed cols
    unsigned long long r0a = 0ull, r0b = 0ull, r1a = 0ull, r1b = 0ull;
    int a0 = row0 * 32, a1 = a0 + 32;
#pragma unroll 8
    for (int kk = 0; kk < 32; kk++) {
        float4 ha = A4[a0 + kk];
        float4 hb = A4[a1 + kk];
        ulonglong2 w0 = W2[(4 * kk + 0) * 16 + tx];
        ulonglong2 w1 = W2[(4 * kk + 1) * 16 + tx];
        ulonglong2 w2 = W2[(4 * kk + 2) * 16 + tx];
        ulonglong2 w3 = W2[(4 * kk + 3) * 16 + tx];
        unsigned long long p;
        p = pack2s(ha.x); fma2(r0a, p, w0.x); fma2(r0b, p, w0.y);
        p = pack2s(ha.y); fma2(r0a, p, w1.x); fma2(r0b, p, w1.y);
        p = pack2s(ha.z); fma2(r0a, p, w2.x); fma2(r0b, p, w2.y);
        p = pack2s(ha.w); fma2(r0a, p, w3.x); fma2(r0b, p, w3.y);
        p = pack2s(hb.x); fma2(r1a, p, w0.x); fma2(r1b, p, w0.y);
        p = pack2s(hb.y); fma2(r1a, p, w1.x); fma2(r1b, p, w1.y);
        p = pack2s(hb.z); fma2(r1a, p, w2.x); fma2(r1b, p, w2.y);
        p = pack2s(hb.w); fma2(r1a, p, w3.x); fma2(r1b, p, w3.y);
    }
    float2 u0 = unpack2(r0a), u1 = unpack2(r0b);
    float2 u2 = unpack2(r1a), u3 = unpack2(r1b);
    float4 acc0 = make_float4(u0.x, u0.y, u1.x, u1.y);
    float4 acc1 = make_float4(u2.x, u2.y, u3.x, u3.y);

    float4* O4 = reinterpret_cast<float4*>(out);
    O4[row0 * 16 + tx] = acc0;
    O4[(row0 + 1) * 16 + tx] = acc1;

    if (r < RREL) {
        const float4* al4 = reinterpret_cast<const float4*>(al + r * HD);
        const float4* ar4 = reinterpret_cast<const float4*>(ar + r * HD);
        float4 av = al4[tx], bv = ar4[tx];
        float pl0 = dot4(acc0, av), pr0 = dot4(acc0, bv);
        float pl1 = dot4(acc1, av), pr1 = dot4(acc1, bv);
#pragma unroll
        for (int o = 1; o < 8; o <<= 1) {
            pl0 += __shfl_xor_sync(0xffffffffu, pl0, o);
            pr0 += __shfl_xor_sync(0xffffffffu, pr0, o);
            pl1 += __shfl_xor_sync(0xffffffffu, pl1, o);
            pr1 += __shfl_xor_sync(0xffffffffu, pr1, o);
        }
        if ((tx & 7) == 0) {
            int hh = tx >> 3;
            reinterpret_cast<float2*>(&g_elr[r][row0])[hh]     = make_float2(pl0, pr0);
            reinterpret_cast<float2*>(&g_elr[r][row0 + 1])[hh] = make_float2(pl1, pr1);
        }
    }
}

// ---------------- fused per-dst softmax + hop-0 gather (warp per (r,dst)) ----------------
__global__ void softmax_hop0() {
    int gt = blockIdx.x * blockDim.x + threadIdx.x;
    int w = gt >> 5, lane = gt & 31;                 // w in [0, RREL*NODES), exact grid
    int r = w / NODES, d = w - r * NODES;
    int off = g_off[r][d], deg = g_off[r][d + 1] - off;
    const float* __restrict__ hin = g_x[r];
    float2 acc = {0.f, 0.f};

    if (deg == 0) {
        reinterpret_cast<float2*>(g_hops[0][r] + (d << 6))[lane] = acc;
        return;
    }
    float4 dv = g_elr[r][d];
    float er0 = dv.y, er1 = dv.w;
    const float4* __restrict__ rec = g_adj[r] + off;
    bool hi = lane >= 16;

    if (deg <= 32) {
        int s = 0;
        float l0 = -1e30f, l1 = -1e30f;
        if (lane < deg) {
            s = g_csr_src[r][off + lane];
            float4 sv = g_elr[r][s];
            l0 = sv.x + er0;
            l1 = sv.z + er1;
            l0 = l0 > 0.f ? l0 : 0.2f * l0;
            l1 = l1 > 0.f ? l1 : 0.2f * l1;
        }
        float m0 = wmax(l0), m1 = wmax(l1);
        float e0 = (lane < deg) ? __expf(l0 - m0) : 0.f;
        float e1 = (lane < deg) ? __expf(l1 - m1) : 0.f;
        float s0 = wsum(e0), s1 = wsum(e1);
        float a0 = e0 / fmaxf(s0, 1e-9f);
        float a1 = e1 / fmaxf(s1, 1e-9f);
        if (lane < deg)
            g_adj[r][off + lane] = make_float4(__int_as_float(s), a0, a1, 0.f);
        __syncwarp();
        // gather via record re-read (uniform loads, matches hop_gather structure)
#pragma unroll 4
        for (int i = 0; i < deg; i++) {
            float4 q = rec[i];
            int sj = __float_as_int(q.x);
            float a = hi ? q.z : q.y;
            float2 v = reinterpret_cast<const float2*>(hin + (sj << 6))[lane];
            acc.x = fmaf(a, v.x, acc.x);
            acc.y = fmaf(a, v.y, acc.y);
        }
    } else {
        // generic path (rare, deg>32)
        float m0 = -1e30f, m1 = -1e30f;
        for (int i = lane; i < deg; i += 32) {
            int s = g_csr_src[r][off + i];
            float4 sv = g_elr[r][s];
            float l0 = sv.x + er0;
            float l1 = sv.z + er1;
            l0 = l0 > 0.f ? l0 : 0.2f * l0;
            l1 = l1 > 0.f ? l1 : 0.2f * l1;
            g_adj[r][off + i] = make_float4(__int_as_float(s), l0, l1, 0.f);
            m0 = fmaxf(m0, l0);
            m1 = fmaxf(m1, l1);
        }
        m0 = wmax(m0); m1 = wmax(m1);
        float s0 = 0.f, s1 = 0.f;
        for (int i = lane; i < deg; i += 32) {
            float4 q = g_adj[r][off + i];
            q.y = __expf(q.y - m0);
            q.z = __expf(q.z - m1);
            g_adj[r][off + i] = q;
            s0 += q.y; s1 += q.z;
        }
        s0 = wsum(s0); s1 = wsum(s1);
        float i0 = 1.f / fmaxf(s0, 1e-9f);
        float i1 = 1.f / fmaxf(s1, 1e-9f);
        for (int i = lane; i < deg; i += 32) {
            float4 q = g_adj[r][off + i];
            g_adj[r][off + i] = make_float4(q.x, q.y * i0, q.z * i1, 0.f);
        }
        __syncwarp();
        for (int i = 0; i < deg; i++) {
            float4 q = rec[i];
            int sj = __float_as_int(q.x);
            float a = hi ? q.z : q.y;
            float2 v = reinterpret_cast<const float2*>(hin + (sj << 6))[lane];
            acc.x = fmaf(a, v.x, acc.x);
            acc.y = fmaf(a, v.y, acc.y);
        }
    }
    reinterpret_cast<float2*>(g_hops[0][r] + (d << 6))[lane] = acc;
}

// ---------------- diffusion hops 1..K-1: uniform record loop ----------------
__global__ void hop_gather(int k) {
    int gt = blockIdx.x * blockDim.x + threadIdx.x;
    int w = gt >> 5, lane = gt & 31;                 // warp per (r,dst)
    int r = w / NODES, d = w - r * NODES;
    int off = g_off[r][d], deg = g_off[r][d + 1] - off;
    const float* __restrict__ hin = g_hops[k - 1][r];
    const float4* __restrict__ rec = g_adj[r] + off;
    bool hi = lane >= 16;
    float2 acc = {0.f, 0.f};
#pragma unroll 4
    for (int i = 0; i < deg; i++) {
        float4 q = rec[i];                           // uniform -> warp broadcast, 1 line
        int s = __float_as_int(q.x);
        float a = hi ? q.z : q.y;
        float2 v = reinterpret_cast<const float2*>(hin + (s << 6))[lane];
        acc.x = fmaf(a, v.x, acc.x);
        acc.y = fmaf(a, v.y, acc.y);
    }
    reinterpret_cast<float2*>(g_hops[k][r] + (d << 6))[lane] = acc;
}

// ---------------- hop attention + mix: 4 lanes per (n,h), 8 pairs per warp ----------------
// lane layout: p = lane>>2 (pair in warp, 0..7), sub = lane&3 (8 dims each)
// global pair gp = warpId*8 + p; n = gp>>1, hh = gp&1  -> hh == bit2 of lane -> shfl_xor(4) swaps heads
__global__ void hop_mix_final(const float* __restrict__ hal, const float* __restrict__ har,
                              float* __restrict__ out) {
    int gt = blockIdx.x * blockDim.x + threadIdx.x;
    int w = gt >> 5, lane = gt & 31;                 // w in [0, NODES*NH/8), exact grid
    int p = lane >> 2, sub = lane & 3;
    int gp = w * 8 + p;
    int n = gp >> 1, hh = gp & 1;
    int base = (n << 6) + (hh << 5) + sub * 8;       // 8 consecutive dims

    const float4* acc4 = reinterpret_cast<const float4*>(g_acc + base);
    float4 accA = acc4[0], accB = acc4[1];

    const float4* hal4 = reinterpret_cast<const float4*>(hal);
    const float4* har4 = reinterpret_cast<const float4*>(har);

#pragma unroll
    for (int r = 0; r < RREL; r++) {
        int aidx = (r * HD + hh * DD) / 4 + sub * 2;
        float4 alA = hal4[aidx], alB = hal4[aidx + 1];
        float4 arA = har4[aidx], arB = har4[aidx + 1];

        float4 nhA[KHOP + 1], nhB[KHOP + 1];
        float lg[KHOP + 1];
#pragma unroll
        for (int k = 0; k < KHOP + 1; k++) {
            const float* hsrc = (k == 0) ? g_x[r] : g_hops[k - 1][r];
            const float4* h4 = reinterpret_cast<const float4*>(hsrc + base);
            float4 vA = h4[0], vB = h4[1];
            float ss = dot4(vA, vA) + dot4(vB, vB);
            ss = qsum(ss);
            float sc = 1.f / fmaxf(sqrtf(ss), 1e-9f);
            nhA[k] = make_float4(vA.x * sc, vA.y * sc, vA.z * sc, vA.w * sc);
            nhB[k] = make_float4(vB.x * sc, vB.y * sc, vB.z * sc, vB.w * sc);
            lg[k] = qsum(dot4(nhA[k], alA) + dot4(nhB[k], alB));
        }
        float hr = qsum(dot4(nhA[0], arA) + dot4(nhB[0], arB));
        float m = -1e30f;
#pragma unroll
        for (int k = 0; k < KHOP + 1; k++) {
            float x = lg[k] + hr;
            lg[k] = x > 0.f ? x : 0.2f * x;
            m = fmaxf(m, lg[k]);
        }
        float s = 0.f, wk[KHOP + 1];
#pragma unroll
        for (int k = 0; k < KHOP + 1; k++) { wk[k] = __expf(lg[k] - m); s += wk[k]; }
        float inv = 1.f / s;
        float4 mixA = make_float4(0.f, 0.f, 0.f, 0.f);
        float4 mixB = make_float4(0.f, 0.f, 0.f, 0.f);
#pragma unroll
        for (int k = 0; k < KHOP + 1; k++) {
            float c = wk[k] * inv;
            mixA.x = fmaf(c, nhA[k].x, mixA.x); mixA.y = fmaf(c, nhA[k].y, mixA.y);
            mixA.z = fmaf(c, nhA[k].z, mixA.z); mixA.w = fmaf(c, nhA[k].w, mixA.w);
            mixB.x = fmaf(c, nhB[k].x, mixB.x); mixB.y = fmaf(c, nhB[k].y, mixB.y);
            mixB.z = fmaf(c, nhB[k].z, mixB.z); mixB.w = fmaf(c, nhB[k].w, mixB.w);
        }
        float wr = g_w[r];
        accA.x = fmaf(wr, mixA.x, accA.x); accA.y = fmaf(wr, mixA.y, accA.y);
        accA.z = fmaf(wr, mixA.z, accA.z); accA.w = fmaf(wr, mixA.w, accA.w);
        accB.x = fmaf(wr, mixB.x, accB.x); accB.y = fmaf(wr, mixB.y, accB.y);
        accB.z = fmaf(wr, mixB.z, accB.z); accB.w = fmaf(wr, mixB.w, accB.w);
    }
    // head exchange: shfl_xor(4) flips hh (lane bit 2)
    float oAx = __shfl_xor_sync(0xffffffffu, accA.x, 4);
    float oAy = __shfl_xor_sync(0xffffffffu, accA.y, 4);
    float oAz = __shfl_xor_sync(0xffffffffu, accA.z, 4);
    float oAw = __shfl_xor_sync(0xffffffffu, accA.w, 4);
    float oBx = __shfl_xor_sync(0xffffffffu, accB.x, 4);
    float oBy = __shfl_xor_sync(0xffffffffu, accB.y, 4);
    float oBz = __shfl_xor_sync(0xffffffffu, accB.z, 4);
    float oBw = __shfl_xor_sync(0xffffffffu, accB.w, 4);
    if (hh == 0) {
        float4* o4 = reinterpret_cast<float4*>(out + n * DD + sub * 8);
        o4[0] = make_float4(0.5f * (accA.x + oAx), 0.5f * (accA.y + oAy),
                            0.5f * (accA.z + oAz), 0.5f * (accA.w + oAw));
        o4[1] = make_float4(0.5f * (accB.x + oBx), 0.5f * (accB.y + oBy),
                            0.5f * (accB.z + oBz), 0.5f * (accB.w + oBw));
    }
}

// ---------------- launch: fork/join so CSR build overlaps setup+GEMM ----------------
extern "C" void kernel_launch(void* const* d_in, const int* in_sizes, int n_in,
                              void* d_out, int out_size) {
    const float* h    = (const float*)d_in[0];
    const int*   src  = (const int*)d_in[1];
    const int*   dst  = (const int*)d_in[2];
    const float* fcw  = (const float*)d_in[3];
    const float* rsw  = (const float*)d_in[4];
    const float* al   = (const float*)d_in[5];
    const float* ar   = (const float*)d_in[6];
    const float* hal  = (const float*)d_in[7];
    const float* har  = (const float*)d_in[8];
    const float* wrel = (const float*)d_in[9];
    const float* brel = (const float*)d_in[10];
    float* out = (float*)d_out;

    static cudaStream_t s2 = nullptr;
    static cudaEvent_t evRoot = nullptr, evCsr = nullptr;
    if (s2 == nullptr) {
        cudaStreamCreateWithFlags(&s2, cudaStreamNonBlocking);
        cudaEventCreateWithFlags(&evRoot, cudaEventDisableTiming);
        cudaEventCreateWithFlags(&evCsr, cudaEventDisableTiming);
    }

    void* deg_p = nullptr;
    cudaGetSymbolAddress(&deg_p, g_deg);

    const int reBlocks = (RREL * EDG) / 256;                 // 6250 exact

    // fork: side stream builds CSR while main stream does setup + GEMMs
    cudaEventRecord(evRoot, 0);
    cudaStreamWaitEvent(s2, evRoot, 0);

    // side stream: CSR chain
    cudaMemsetAsync(deg_p, 0, (size_t)RREL * NODES * sizeof(int), s2);
    csr_count<<<reBlocks, 256, 0, s2>>>(dst);
    csr_scan<<<RREL, 1024, 0, s2>>>();
    csr_fill<<<reBlocks, 256, 0, s2>>>(src, dst);
    cudaEventRecord(evCsr, s2);

    // main stream: setup (16 blocks) + 5 fc GEMMs (+attn epilogue) + combined residual GEMM
    setup_kernel<<<16, 512>>>(wrel, brel, rsw);
    dim3 gg(NODES / 32, RREL + 1);
    gemm_all<<<gg, 256>>>(h, fcw, al, ar);

    // join: softmax needs both CSR and GEMM results
    cudaStreamWaitEvent(0, evCsr, 0);

    const int wBlocks = (RREL * NODES * 32) / 256;           // 12500 exact
    softmax_hop0<<<wBlocks, 256>>>();
    for (int k = 1; k < KHOP; k++)
        hop_gather<<<wBlocks, 256>>>(k);

    // 4-lane hop mix: NODES*NH/8 pairs per warp -> 5000 warps -> 625 blocks
    hop_mix_final<<<(NODES * NH * 4) / 256, 256>>>(hal, har, out);
}